// round 13
// baseline (speedup 1.0000x reference)
#include <cuda_runtime.h>
#include <math.h>
#include <cstdint>

#define Bn 4
#define Tn 8
#define Hn 256
#define Wn 256
#define NPIX (Bn*Tn*Hn*Wn)   // 2,097,152 elements per field

typedef unsigned long long u64;

// Scratch (static device globals -- no allocation allowed)
// fields: 0:kappa^2 1:m1 2:m2 3:Hxx 4:(Hxy+Hyx) 5:unused 6:Hyy 7:D
__device__ float g_fields[8][NPIX];
__device__ __align__(16) float g_ws[72 * 64];   // transposed+permuted weights [k][o_slot]
__device__ double g_acc[2];                     // [0]=sum(D r^2) [1]=sum(log D)

__global__ void init_acc_kernel() {
    g_acc[0] = 0.0;
    g_acc[1] = 0.0;
}

__global__ void dummy_kernel() {}

// One-off: transpose + permute cw -> g_ws[k][o_slot].
// Warps 4/5 get interleaved (Hxy, Hyx) channel pairs:
//   tn==4, slot j: j2=j>>1, half=j&1 -> src = 32 + 8*half + j2      (t = j2)
//   tn==5, slot j: j2=j>>1, half=j&1 -> src = 32 + 8*half + 4 + j2  (t = 4+j2)
__global__ __launch_bounds__(256) void transpose_w_kernel(const float* __restrict__ cw)
{
    int i = blockIdx.x * 256 + threadIdx.x;   // i = k*64 + o_slot
    if (i < 72 * 64) {
        int k = i >> 6, o_slot = i & 63;
        int tn = o_slot >> 3, j = o_slot & 7;
        int src;
        if (tn == 4)      { int j2 = j >> 1, half = j & 1; src = 32 + 8 * half + j2; }
        else if (tn == 5) { int j2 = j >> 1, half = j & 1; src = 32 + 8 * half + 4 + j2; }
        else               src = o_slot;
        g_ws[k * 64 + o_slot] = cw[src * 72 + k];
    }
}

// ---------------------------------------------------------------------------
// packed f32x2 helpers (Blackwell)
// ---------------------------------------------------------------------------
__device__ __forceinline__ u64 fma2(u64 a, u64 b, u64 c) {
    u64 d;
    asm("fma.rn.f32x2 %0, %1, %2, %3;" : "=l"(d) : "l"(a), "l"(b), "l"(c));
    return d;
}
__device__ __forceinline__ void unpack2(u64 v, float& lo, float& hi) {
    unsigned int a, b;
    asm("mov.b64 {%0, %1}, %2;" : "=r"(a), "=r"(b) : "l"(v));
    lo = __uint_as_float(a);
    hi = __uint_as_float(b);
}

// ---------------------------------------------------------------------------
// Kernel 1: 3x3 conv (8 -> 64 channels), f32x2 FMA.
// x tile stored in smem PRE-DUPLICATED as float2 (v,v): window load is one
// LDS.64 feeding fma2 directly (no mov.b64 dup on the critical path).
// Tile: 32 wide x 4 tall. 256 threads, warp id = slot group (8 slots).
// Each thread: 4 rows x 4 slot-pairs = 16 u64 accumulators.
// ---------------------------------------------------------------------------
#define TW 32
#define TH 4

__global__ __launch_bounds__(256, 4) void conv_kernel(const float* __restrict__ x)
{
    __shared__ __align__(16) float2 xs2[8][TH + 2][TW + 3];  // dup pairs (13.4KB)
    __shared__ __align__(16) float ws[72 * 64];              // [k][o_slot] (18KB)

    const int tid = threadIdx.x;
    const int b  = blockIdx.z;
    const int h0 = blockIdx.y * TH;
    const int w0 = blockIdx.x * TW;

    // coalesced copy of pre-transposed weights (float4)
    {
        const float4* src = (const float4*)g_ws;
        float4* dst = (float4*)ws;
        #pragma unroll
        for (int i = tid; i < 72 * 16; i += 256)
            dst[i] = src[i];
    }
    // x tile with halo 1 (zero Dirichlet), duplicated (v,v)
    for (int i = tid; i < 8 * (TH + 2) * (TW + 2); i += 256) {
        int ci  = i / ((TH + 2) * (TW + 2));
        int rem = i % ((TH + 2) * (TW + 2));
        int yy  = rem / (TW + 2);
        int xx  = rem % (TW + 2);
        int gy = h0 - 1 + yy, gx = w0 - 1 + xx;
        float v = 0.f;
        if (gy >= 0 && gy < Hn && gx >= 0 && gx < Wn)
            v = x[(((b * Tn) + ci) * Hn + gy) * Wn + gx];
        xs2[ci][yy][xx] = make_float2(v, v);
    }
    __syncthreads();

    const int tn = tid >> 5;   // warp = slot group (0..7)
    const int tm = tid & 31;   // pixel column within tile

    u64 acc2[TH][4];
    #pragma unroll
    for (int i = 0; i < TH; i++)
        #pragma unroll
        for (int j = 0; j < 4; j++) acc2[i][j] = 0ull;

    const int obase = tn * 8;
    #pragma unroll 4
    for (int ci = 0; ci < 8; ci++) {
        #pragma unroll
        for (int kx = 0; kx < 3; kx++) {
            // 6-row duplicated column window at tm+kx: direct LDS.64 per row
            u64 xd[TH + 2];
            #pragma unroll
            for (int r = 0; r < TH + 2; r++)
                xd[r] = *(const u64*)&xs2[ci][r][tm + kx];
            #pragma unroll
            for (int ky = 0; ky < 3; ky++) {
                const int k = ci * 9 + ky * 3 + kx;
                const ulonglong2* wp = (const ulonglong2*)&ws[k * 64 + obase];
                ulonglong2 wa = wp[0];
                ulonglong2 wb = wp[1];
                #pragma unroll
                for (int i = 0; i < TH; i++) {
                    u64 xv = xd[i + ky];
                    acc2[i][0] = fma2(xv, wa.x, acc2[i][0]);
                    acc2[i][1] = fma2(xv, wa.y, acc2[i][1]);
                    acc2[i][2] = fma2(xv, wb.x, acc2[i][2]);
                    acc2[i][3] = fma2(xv, wb.y, acc2[i][3]);
                }
            }
        }
    }

    float lsum = 0.f;
    #pragma unroll
    for (int i = 0; i < TH; i++) {
        const int h = h0 + i;
        #pragma unroll
        for (int j2 = 0; j2 < 4; j2++) {
            float t0, t1;
            unpack2(acc2[i][j2], t0, t1);
            if (tn == 4 || tn == 5) {
                // pair = (Hxy[t], Hyx[t]) -> merged field 4
                int tch = (tn == 4) ? j2 : 4 + j2;
                float r = 0.1f * (tanhf(t0) + tanhf(t1));
                g_fields[4][(((b * Tn) + tch) * Hn + h) * Wn + w0 + tm] = r;
            } else {
                float r0, r1;
                if (tn == 0) {                       // kappa -> kappa^2
                    float s0 = 1.f / (1.f + expf(-t0));
                    float s1 = 1.f / (1.f + expf(-t1));
                    float k0 = s0 * 0.99f + 0.01f;
                    float k1 = s1 * 0.99f + 0.01f;
                    r0 = k0 * k0; r1 = k1 * k1;
                } else if (tn == 1 || tn == 2) {     // m1, m2 raw
                    r0 = t0; r1 = t1;
                } else if (tn == 3 || tn == 6) {     // Hxx, Hyy
                    r0 = (1.f / (1.f + expf(-t0))) * 0.99f + 0.01f;
                    r1 = (1.f / (1.f + expf(-t1))) * 0.99f + 0.01f;
                } else {                             // tau -> D = 1/tau^2
                    float s0 = 1.f / (1.f + expf(-t0));
                    float s1 = 1.f / (1.f + expf(-t1));
                    float ta0 = s0 * 9.9f + 0.1f;
                    float ta1 = s1 * 9.9f + 0.1f;
                    r0 = 1.f / (ta0 * ta0);
                    r1 = 1.f / (ta1 * ta1);
                    lsum += logf(r0) + logf(r1);
                }
                const int j0 = 2 * j2;
                g_fields[tn][(((b * Tn) + j0)     * Hn + h) * Wn + w0 + tm] = r0;
                g_fields[tn][(((b * Tn) + j0 + 1) * Hn + h) * Wn + w0 + tm] = r1;
            }
        }
    }

    if (tn == 7) {   // accumulate logdet(D)
        #pragma unroll
        for (int off = 16; off; off >>= 1)
            lsum += __shfl_down_sync(0xffffffffu, lsum, off);
        if (tm == 0) atomicAdd(&g_acc[1], (double)lsum);
    }
}

// ---------------------------------------------------------------------------
// Fused stencil: per 32x32 output tile, compute v=A(x) on the 34x34 region
// in smem (caching fields), then r = x + A(v) - x_prev and reduce sum(D r^2).
// ---------------------------------------------------------------------------
__global__ __launch_bounds__(256) void stencil_fused_kernel(const float* __restrict__ x)
{
    __shared__ float xs[36][37];           // x with halo 2
    __shared__ float vs[34][35];           // v = A(x) on halo-1 region
    __shared__ float fc[6][34][35];        // cached fields 0,1,2,3,4,6
    __shared__ float red[8];

    const int tid  = threadIdx.x;
    const int tile = blockIdx.x;           // 0..63
    const int t    = blockIdx.y;
    const int b    = blockIdx.z;
    const int h0   = (tile >> 3) * 32;
    const int w0   = (tile & 7) * 32;
    const int base = ((b * Tn + t) * Hn) * Wn;

    // phase 1: xs = x with halo 2 (zero Dirichlet)
    for (int i = tid; i < 36 * 36; i += 256) {
        int yy = i / 36, xx = i % 36;
        int gh = h0 - 2 + yy, gw = w0 - 2 + xx;
        float v = 0.f;
        if (gh >= 0 && gh < Hn && gw >= 0 && gw < Wn)
            v = x[base + gh * Wn + gw];
        xs[yy][xx] = v;
    }
    __syncthreads();

    // phase 2: v over 34x34 (global coords h0-1+vy, w0-1+vx); cache fields
    for (int i = tid; i < 34 * 34; i += 256) {
        int vy = i / 34, vx = i % 34;
        int gh = h0 - 1 + vy, gw = w0 - 1 + vx;
        float q0 = 0.f, q1 = 0.f, q2 = 0.f, q3 = 0.f, q4 = 0.f, q6 = 0.f;
        float vval = 0.f;
        if (gh >= 0 && gh < Hn && gw >= 0 && gw < Wn) {
            int p = base + gh * Wn + gw;
            q0 = g_fields[0][p]; q1 = g_fields[1][p]; q2 = g_fields[2][p];
            q3 = g_fields[3][p]; q4 = g_fields[4][p]; q6 = g_fields[6][p];
            float c   = xs[vy + 1][vx + 1];
            float xl  = xs[vy + 1][vx],     xr  = xs[vy + 1][vx + 2];
            float xu  = xs[vy][vx + 1],     xd  = xs[vy + 2][vx + 1];
            float xul = xs[vy][vx],         xur = xs[vy][vx + 2];
            float xdl = xs[vy + 2][vx],     xdr = xs[vy + 2][vx + 2];
            float dx  = 0.5f  * (xr - xl);
            float dy  = 0.5f  * (xd - xu);
            float dxx = xr + xl - 2.f * c;
            float dyy = xd + xu - 2.f * c;
            float dxy = 0.25f * ((xdr - xur) - (xdl - xul));
            vval = q0 * c + q1 * dx + q2 * dy - (q3 * dxx + q6 * dyy + q4 * dxy);
        }
        vs[vy][vx] = vval;
        fc[0][vy][vx] = q0; fc[1][vy][vx] = q1; fc[2][vy][vx] = q2;
        fc[3][vy][vx] = q3; fc[4][vy][vx] = q4; fc[5][vy][vx] = q6;
    }
    __syncthreads();

    // phase 3: 4 output pixels per thread (row oy, cols ox4..ox4+3)
    const int oy  = tid >> 3;           // 0..31
    const int ox4 = (tid & 7) * 4;      // 0..28
    const int gh  = h0 + oy;
    const int p   = base + gh * Wn + w0 + ox4;

    float4 f7 = *(const float4*)&g_fields[7][p];
    float4 xp = make_float4(0.f, 0.f, 0.f, 0.f);
    if (t > 0) xp = *(const float4*)&x[p - Hn * Wn];
    float f7a[4] = {f7.x, f7.y, f7.z, f7.w};
    float xpa[4] = {xp.x, xp.y, xp.z, xp.w};

    float val = 0.f;
    #pragma unroll
    for (int j = 0; j < 4; j++) {
        int vy = oy + 1, vx = ox4 + j + 1;
        float c   = vs[vy][vx];
        float xl  = vs[vy][vx - 1],     xr  = vs[vy][vx + 1];
        float xu  = vs[vy - 1][vx],     xd  = vs[vy + 1][vx];
        float xul = vs[vy - 1][vx - 1], xur = vs[vy - 1][vx + 1];
        float xdl = vs[vy + 1][vx - 1], xdr = vs[vy + 1][vx + 1];
        float dx  = 0.5f  * (xr - xl);
        float dy  = 0.5f  * (xd - xu);
        float dxx = xr + xl - 2.f * c;
        float dyy = xd + xu - 2.f * c;
        float dxy = 0.25f * ((xdr - xur) - (xdl - xul));
        float Av  = fc[0][vy][vx] * c + fc[1][vy][vx] * dx + fc[2][vy][vx] * dy
                  - (fc[3][vy][vx] * dxx + fc[5][vy][vx] * dyy + fc[4][vy][vx] * dxy);
        float xv  = xs[oy + 2][ox4 + j + 2];
        float r   = xv + Av - xpa[j];
        val += f7a[j] * r * r;
    }

    // block reduction (256 threads) -> double atomic
    #pragma unroll
    for (int off = 16; off; off >>= 1)
        val += __shfl_down_sync(0xffffffffu, val, off);
    const int lane = tid & 31;
    const int wid  = tid >> 5;
    if (lane == 0) red[wid] = val;
    __syncthreads();
    if (wid == 0) {
        float s = (lane < 8) ? red[lane] : 0.f;
        #pragma unroll
        for (int off = 4; off; off >>= 1)
            s += __shfl_down_sync(0xffffffffu, s, off);
        if (lane == 0) atomicAdd(&g_acc[0], (double)s);
    }
}

__global__ void finalize_kernel(float* __restrict__ out)
{
    out[0] = (float)(0.5 * (g_acc[0] - g_acc[1]));
}

// ---------------------------------------------------------------------------
extern "C" void kernel_launch(void* const* d_in, const int* in_sizes, int n_in,
                              void* d_out, int out_size)
{
    const float* x  = (const float*)d_in[0];
    const float* cw = (const float*)d_in[1];
    float* out = (float*)d_out;

    init_acc_kernel<<<1, 1>>>();          // kernel 1
    transpose_w_kernel<<<18, 256>>>(cw);  // kernel 2
    dummy_kernel<<<1, 1>>>();             // kernel 3 (ncu captures kernel 4)

    dim3 gA(Wn / TW, Hn / TH, Bn);        // 8 x 64 x 4 = 2048 blocks
    conv_kernel<<<gA, 256>>>(x);          // kernel 4 -> ncu target

    dim3 gF(64, Tn, Bn);                  // 64 tiles x 8 t x 4 b = 2048 blocks
    stencil_fused_kernel<<<gF, 256>>>(x);

    finalize_kernel<<<1, 1>>>(out);
}

// round 14
// speedup vs baseline: 2.3811x; 2.3811x over previous
#include <cuda_runtime.h>
#include <cuda_bf16.h>
#include <math.h>
#include <cstdint>

#define Bn 4
#define Tn 8
#define Hn 256
#define Wn 256
#define NPIX (Bn*Tn*Hn*Wn)   // 2,097,152 elements per field

// Scratch (static device globals -- no allocation allowed)
// fields: 0:kappa^2 1:m1 2:m2 3:Hxx 4:(Hxy+Hyx) 5:unused 6:Hyy 7:D
__device__ float g_fields[8][NPIX];
__device__ __align__(16) __nv_bfloat16 g_wsb[64 * 84];  // permuted bf16 weights [o][k], k-padded
__device__ double g_acc[2];                             // [0]=sum(D r^2) [1]=sum(log D)

__global__ void init_acc_kernel() {
    g_acc[0] = 0.0;
    g_acc[1] = 0.0;
}

__global__ void dummy_kernel() {}

// One-off: permute + transpose + bf16-convert cw -> g_wsb[o_slot][k] (k padded to 84).
// Slot permutation: groups 4/5 interleave (Hxy[t], Hyx[t]) channel pairs:
//   tn==4, slot j: j2=j>>1, half=j&1 -> src = 32 + 8*half + j2      (t = j2)
//   tn==5, slot j: j2=j>>1, half=j&1 -> src = 32 + 8*half + 4 + j2  (t = 4+j2)
__global__ __launch_bounds__(256) void transpose_w_kernel(const float* __restrict__ cw)
{
    int i = blockIdx.x * 256 + threadIdx.x;   // i = o_slot*84 + k
    if (i < 64 * 84) {
        int o_slot = i / 84, k = i % 84;
        int tn = o_slot >> 3, j = o_slot & 7;
        int src = o_slot;
        if (tn == 4)      { int j2 = j >> 1, half = j & 1; src = 32 + 8 * half + j2; }
        else if (tn == 5) { int j2 = j >> 1, half = j & 1; src = 32 + 8 * half + 4 + j2; }
        float v = (k < 72) ? cw[src * 72 + k] : 0.f;
        g_wsb[i] = __float2bfloat16(v);
    }
}

// ---------------------------------------------------------------------------
// mma.sync m16n8k16 bf16 (sm_80+ baseline PTX -- compiles for compute_103)
// ---------------------------------------------------------------------------
__device__ __forceinline__ void mma16816(float* d,
                                         uint32_t a0, uint32_t a1, uint32_t a2, uint32_t a3,
                                         uint32_t b0, uint32_t b1)
{
    asm volatile(
        "mma.sync.aligned.m16n8k16.row.col.f32.bf16.bf16.f32 "
        "{%0,%1,%2,%3}, {%4,%5,%6,%7}, {%8,%9}, {%0,%1,%2,%3};"
        : "+f"(d[0]), "+f"(d[1]), "+f"(d[2]), "+f"(d[3])
        : "r"(a0), "r"(a1), "r"(a2), "r"(a3), "r"(b0), "r"(b1));
}

// ---------------------------------------------------------------------------
// Kernel 1: 3x3 conv (8 -> 64 ch) as tensor-core GEMM:
//   D[128 pix, 64 ch] = A_im2col[128, 80] * B[64, 80]^T  (bf16 in, f32 acc)
// Tile: 32 wide x 4 tall = 128 pixels. 256 threads = 8 warps.
// Warp w: M-strip rows [16w, 16w+16); 5 k-steps x 8 n-tiles of mma.sync.
// n-tile == nonlinearity group (permuted weights).
// ---------------------------------------------------------------------------
#define TW 32
#define TH 4
#define KS 84   // padded K stride (42 words -> conflict-free ldmatrix-free frags)

__global__ __launch_bounds__(256) void conv_kernel(const float* __restrict__ x)
{
    __shared__ float xs[8][TH + 2][TW + 2];                 // 6.5 KB
    __shared__ __align__(16) __nv_bfloat16 As[128][KS];     // 21.0 KB
    __shared__ __align__(16) __nv_bfloat16 Bs[64][KS];      // 10.5 KB
    __shared__ float red[8];

    const int tid = threadIdx.x;
    const int b  = blockIdx.z;
    const int h0 = blockIdx.y * TH;
    const int w0 = blockIdx.x * TW;

    // B copy (coalesced uint4): 64*84*2 B = 672 uint4
    {
        const uint4* srcb = (const uint4*)g_wsb;
        uint4* dstb = (uint4*)&Bs[0][0];
        #pragma unroll
        for (int i = tid; i < 672; i += 256)
            dstb[i] = srcb[i];
    }
    // x tile with halo 1 (zero Dirichlet)
    for (int i = tid; i < 8 * (TH + 2) * (TW + 2); i += 256) {
        int ci  = i / ((TH + 2) * (TW + 2));
        int rem = i % ((TH + 2) * (TW + 2));
        int yy  = rem / (TW + 2);
        int xx  = rem % (TW + 2);
        int gy = h0 - 1 + yy, gx = w0 - 1 + xx;
        float v = 0.f;
        if (gy >= 0 && gy < Hn && gx >= 0 && gx < Wn)
            v = x[(((b * Tn) + ci) * Hn + gy) * Wn + gx];
        xs[ci][yy][xx] = v;
    }
    __syncthreads();

    // Build im2col A: thread (pix = tid>>1, half = tid&1) writes 18 bf16x2.
    {
        const int pix = tid >> 1;
        const int py = pix >> 5, px = pix & 31;
        if ((tid & 1) == 0) {
            #pragma unroll
            for (int m = 0; m < 18; m++) {
                const int k0 = 2 * m, k1 = 2 * m + 1;
                float f0 = xs[k0 / 9][py + (k0 % 9) / 3][px + (k0 % 3)];
                float f1 = xs[k1 / 9][py + (k1 % 9) / 3][px + (k1 % 3)];
                __nv_bfloat162 p = __float22bfloat162_rn(make_float2(f0, f1));
                *(uint32_t*)&As[pix][2 * m] = *(uint32_t*)&p;
            }
            #pragma unroll
            for (int m = 36; m < 42; m++)         // zero pad k 72..83
                *(uint32_t*)&As[pix][2 * m] = 0u;
        } else {
            #pragma unroll
            for (int m = 18; m < 36; m++) {
                const int k0 = 2 * m, k1 = 2 * m + 1;
                float f0 = xs[k0 / 9][py + (k0 % 9) / 3][px + (k0 % 3)];
                float f1 = xs[k1 / 9][py + (k1 % 9) / 3][px + (k1 % 3)];
                __nv_bfloat162 p = __float22bfloat162_rn(make_float2(f0, f1));
                *(uint32_t*)&As[pix][2 * m] = *(uint32_t*)&p;
            }
        }
    }
    __syncthreads();

    const int wid  = tid >> 5;
    const int lane = tid & 31;
    const int gid  = lane >> 2;   // 0..7
    const int tig  = lane & 3;    // 0..3
    const int m0   = wid * 16;

    float d[8][4];
    #pragma unroll
    for (int nt = 0; nt < 8; nt++)
        #pragma unroll
        for (int c = 0; c < 4; c++) d[nt][c] = 0.f;

    // Mainloop: 5 k-steps x 8 n-tiles
    #pragma unroll
    for (int kb = 0; kb < 80; kb += 16) {
        uint32_t a0 = *(const uint32_t*)&As[m0 + gid]    [kb + 2 * tig];
        uint32_t a1 = *(const uint32_t*)&As[m0 + gid + 8][kb + 2 * tig];
        uint32_t a2 = *(const uint32_t*)&As[m0 + gid]    [kb + 8 + 2 * tig];
        uint32_t a3 = *(const uint32_t*)&As[m0 + gid + 8][kb + 8 + 2 * tig];
        #pragma unroll
        for (int nt = 0; nt < 8; nt++) {
            uint32_t b0 = *(const uint32_t*)&Bs[nt * 8 + gid][kb + 2 * tig];
            uint32_t b1 = *(const uint32_t*)&Bs[nt * 8 + gid][kb + 8 + 2 * tig];
            mma16816(d[nt], a0, a1, a2, a3, b0, b1);
        }
    }

    // Epilogue: per n-tile nonlinearity; D frag c0,c1 = (row gid, ch 2tig,2tig+1),
    // c2,c3 = row gid+8. n-tile == group; lane cols are the merge pairs for 4/5.
    float lsum = 0.f;
    #pragma unroll
    for (int nt = 0; nt < 8; nt++) {
        #pragma unroll
        for (int half = 0; half < 2; half++) {
            float t0 = d[nt][2 * half];
            float t1 = d[nt][2 * half + 1];
            const int r  = m0 + gid + 8 * half;
            const int py = r >> 5, px = r & 31;
            const int h = h0 + py, w = w0 + px;
            if (nt == 4 || nt == 5) {
                const int tch = (nt == 4) ? tig : 4 + tig;
                float rv = 0.1f * (tanhf(t0) + tanhf(t1));
                g_fields[4][(((b * Tn) + tch) * Hn + h) * Wn + w] = rv;
            } else {
                const int j0 = 2 * tig;
                float r0, r1;
                if (nt == 0) {
                    float s0 = 1.f / (1.f + expf(-t0));
                    float s1 = 1.f / (1.f + expf(-t1));
                    float k0 = s0 * 0.99f + 0.01f;
                    float k1 = s1 * 0.99f + 0.01f;
                    r0 = k0 * k0; r1 = k1 * k1;
                } else if (nt == 1 || nt == 2) {
                    r0 = t0; r1 = t1;
                } else if (nt == 3 || nt == 6) {
                    r0 = (1.f / (1.f + expf(-t0))) * 0.99f + 0.01f;
                    r1 = (1.f / (1.f + expf(-t1))) * 0.99f + 0.01f;
                } else {   // nt == 7: tau -> D
                    float s0 = 1.f / (1.f + expf(-t0));
                    float s1 = 1.f / (1.f + expf(-t1));
                    float ta0 = s0 * 9.9f + 0.1f;
                    float ta1 = s1 * 9.9f + 0.1f;
                    r0 = 1.f / (ta0 * ta0);
                    r1 = 1.f / (ta1 * ta1);
                    lsum += logf(r0) + logf(r1);
                }
                g_fields[nt][(((b * Tn) + j0)     * Hn + h) * Wn + w] = r0;
                g_fields[nt][(((b * Tn) + j0 + 1) * Hn + h) * Wn + w] = r1;
            }
        }
    }

    // logdet(D) block reduction
    #pragma unroll
    for (int off = 16; off; off >>= 1)
        lsum += __shfl_down_sync(0xffffffffu, lsum, off);
    if (lane == 0) red[wid] = lsum;
    __syncthreads();
    if (wid == 0) {
        float s = (lane < 8) ? red[lane] : 0.f;
        #pragma unroll
        for (int off = 4; off; off >>= 1)
            s += __shfl_down_sync(0xffffffffu, s, off);
        if (lane == 0) atomicAdd(&g_acc[1], (double)s);
    }
}

// ---------------------------------------------------------------------------
// Fused stencil: per 32x32 output tile, compute v=A(x) on the 34x34 region
// in smem (caching fields), then r = x + A(v) - x_prev and reduce sum(D r^2).
// ---------------------------------------------------------------------------
__global__ __launch_bounds__(256) void stencil_fused_kernel(const float* __restrict__ x)
{
    __shared__ float xs[36][37];           // x with halo 2
    __shared__ float vs[34][35];           // v = A(x) on halo-1 region
    __shared__ float fc[6][34][35];        // cached fields 0,1,2,3,4,6
    __shared__ float red[8];

    const int tid  = threadIdx.x;
    const int tile = blockIdx.x;           // 0..63
    const int t    = blockIdx.y;
    const int b    = blockIdx.z;
    const int h0   = (tile >> 3) * 32;
    const int w0   = (tile & 7) * 32;
    const int base = ((b * Tn + t) * Hn) * Wn;

    // phase 1: xs = x with halo 2 (zero Dirichlet)
    for (int i = tid; i < 36 * 36; i += 256) {
        int yy = i / 36, xx = i % 36;
        int gh = h0 - 2 + yy, gw = w0 - 2 + xx;
        float v = 0.f;
        if (gh >= 0 && gh < Hn && gw >= 0 && gw < Wn)
            v = x[base + gh * Wn + gw];
        xs[yy][xx] = v;
    }
    __syncthreads();

    // phase 2: v over 34x34 (global coords h0-1+vy, w0-1+vx); cache fields
    for (int i = tid; i < 34 * 34; i += 256) {
        int vy = i / 34, vx = i % 34;
        int gh = h0 - 1 + vy, gw = w0 - 1 + vx;
        float q0 = 0.f, q1 = 0.f, q2 = 0.f, q3 = 0.f, q4 = 0.f, q6 = 0.f;
        float vval = 0.f;
        if (gh >= 0 && gh < Hn && gw >= 0 && gw < Wn) {
            int p = base + gh * Wn + gw;
            q0 = g_fields[0][p]; q1 = g_fields[1][p]; q2 = g_fields[2][p];
            q3 = g_fields[3][p]; q4 = g_fields[4][p]; q6 = g_fields[6][p];
            float c   = xs[vy + 1][vx + 1];
            float xl  = xs[vy + 1][vx],     xr  = xs[vy + 1][vx + 2];
            float xu  = xs[vy][vx + 1],     xd  = xs[vy + 2][vx + 1];
            float xul = xs[vy][vx],         xur = xs[vy][vx + 2];
            float xdl = xs[vy + 2][vx],     xdr = xs[vy + 2][vx + 2];
            float dx  = 0.5f  * (xr - xl);
            float dy  = 0.5f  * (xd - xu);
            float dxx = xr + xl - 2.f * c;
            float dyy = xd + xu - 2.f * c;
            float dxy = 0.25f * ((xdr - xur) - (xdl - xul));
            vval = q0 * c + q1 * dx + q2 * dy - (q3 * dxx + q6 * dyy + q4 * dxy);
        }
        vs[vy][vx] = vval;
        fc[0][vy][vx] = q0; fc[1][vy][vx] = q1; fc[2][vy][vx] = q2;
        fc[3][vy][vx] = q3; fc[4][vy][vx] = q4; fc[5][vy][vx] = q6;
    }
    __syncthreads();

    // phase 3: 4 output pixels per thread (row oy, cols ox4..ox4+3)
    const int oy  = tid >> 3;           // 0..31
    const int ox4 = (tid & 7) * 4;      // 0..28
    const int gh  = h0 + oy;
    const int p   = base + gh * Wn + w0 + ox4;

    float4 f7 = *(const float4*)&g_fields[7][p];
    float4 xp = make_float4(0.f, 0.f, 0.f, 0.f);
    if (t > 0) xp = *(const float4*)&x[p - Hn * Wn];
    float f7a[4] = {f7.x, f7.y, f7.z, f7.w};
    float xpa[4] = {xp.x, xp.y, xp.z, xp.w};

    float val = 0.f;
    #pragma unroll
    for (int j = 0; j < 4; j++) {
        int vy = oy + 1, vx = ox4 + j + 1;
        float c   = vs[vy][vx];
        float xl  = vs[vy][vx - 1],     xr  = vs[vy][vx + 1];
        float xu  = vs[vy - 1][vx],     xd  = vs[vy + 1][vx];
        float xul = vs[vy - 1][vx - 1], xur = vs[vy - 1][vx + 1];
        float xdl = vs[vy + 1][vx - 1], xdr = vs[vy + 1][vx + 1];
        float dx  = 0.5f  * (xr - xl);
        float dy  = 0.5f  * (xd - xu);
        float dxx = xr + xl - 2.f * c;
        float dyy = xd + xu - 2.f * c;
        float dxy = 0.25f * ((xdr - xur) - (xdl - xul));
        float Av  = fc[0][vy][vx] * c + fc[1][vy][vx] * dx + fc[2][vy][vx] * dy
                  - (fc[3][vy][vx] * dxx + fc[5][vy][vx] * dyy + fc[4][vy][vx] * dxy);
        float xv  = xs[oy + 2][ox4 + j + 2];
        float r   = xv + Av - xpa[j];
        val += f7a[j] * r * r;
    }

    // block reduction (256 threads) -> double atomic
    #pragma unroll
    for (int off = 16; off; off >>= 1)
        val += __shfl_down_sync(0xffffffffu, val, off);
    const int lane = tid & 31;
    const int wid  = tid >> 5;
    if (lane == 0) red[wid] = val;
    __syncthreads();
    if (wid == 0) {
        float s = (lane < 8) ? red[lane] : 0.f;
        #pragma unroll
        for (int off = 4; off; off >>= 1)
            s += __shfl_down_sync(0xffffffffu, s, off);
        if (lane == 0) atomicAdd(&g_acc[0], (double)s);
    }
}

__global__ void finalize_kernel(float* __restrict__ out)
{
    out[0] = (float)(0.5 * (g_acc[0] - g_acc[1]));
}

// ---------------------------------------------------------------------------
extern "C" void kernel_launch(void* const* d_in, const int* in_sizes, int n_in,
                              void* d_out, int out_size)
{
    const float* x  = (const float*)d_in[0];
    const float* cw = (const float*)d_in[1];
    float* out = (float*)d_out;

    init_acc_kernel<<<1, 1>>>();          // kernel 1
    transpose_w_kernel<<<21, 256>>>(cw);  // kernel 2
    dummy_kernel<<<1, 1>>>();             // kernel 3 (ncu captures kernel 4)

    dim3 gA(Wn / TW, Hn / TH, Bn);        // 8 x 64 x 4 = 2048 blocks
    conv_kernel<<<gA, 256>>>(x);          // kernel 4 -> ncu target

    dim3 gF(64, Tn, Bn);                  // 64 tiles x 8 t x 4 b = 2048 blocks
    stencil_fused_kernel<<<gF, 256>>>(x);

    finalize_kernel<<<1, 1>>>(out);
}

// round 16
// speedup vs baseline: 2.4877x; 1.0448x over previous
#include <cuda_runtime.h>
#include <cuda_bf16.h>
#include <math.h>
#include <cstdint>

#define Bn 4
#define Tn 8
#define Hn 256
#define Wn 256
#define NPIX (Bn*Tn*Hn*Wn)   // 2,097,152 elements per field

// Scratch (static device globals -- no allocation allowed)
// fields: 0:kappa^2 1:m1 2:m2 3:Hxx 4:(Hxy+Hyx) 5:unused 6:Hyy 7:D
__device__ float g_fields[8][NPIX];
__device__ __align__(16) __nv_bfloat16 g_wsb[64 * 88];  // permuted bf16 weights [o][k], k-pad 88
__device__ double g_acc[2];                             // [0]=sum(D r^2) [1]=sum(log D)

__global__ void dummy_kernel() {}

// One-off: permute + transpose + bf16-convert cw -> g_wsb[o_slot][k] (k padded to 88).
// Also zeroes the accumulators (merged init).
// Slot permutation: groups 4/5 interleave (Hxy[t], Hyx[t]) channel pairs.
__global__ __launch_bounds__(256) void transpose_w_kernel(const float* __restrict__ cw)
{
    if (blockIdx.x == 0 && threadIdx.x == 0) {
        g_acc[0] = 0.0;
        g_acc[1] = 0.0;
    }
    int i = blockIdx.x * 256 + threadIdx.x;   // i = o_slot*88 + k
    if (i < 64 * 88) {
        int o_slot = i / 88, k = i % 88;
        int tn = o_slot >> 3, j = o_slot & 7;
        int src = o_slot;
        if (tn == 4)      { int j2 = j >> 1, half = j & 1; src = 32 + 8 * half + j2; }
        else if (tn == 5) { int j2 = j >> 1, half = j & 1; src = 32 + 8 * half + 4 + j2; }
        float v = (k < 72) ? cw[src * 72 + k] : 0.f;
        g_wsb[i] = __float2bfloat16(v);
    }
}

// ---------------------------------------------------------------------------
// Tensor-core primitives (sm_75/80 baseline PTX -- compile for compute_103)
// ---------------------------------------------------------------------------
__device__ __forceinline__ void mma16816(float* d,
                                         uint32_t a0, uint32_t a1, uint32_t a2, uint32_t a3,
                                         uint32_t b0, uint32_t b1)
{
    asm volatile(
        "mma.sync.aligned.m16n8k16.row.col.f32.bf16.bf16.f32 "
        "{%0,%1,%2,%3}, {%4,%5,%6,%7}, {%8,%9}, {%0,%1,%2,%3};"
        : "+f"(d[0]), "+f"(d[1]), "+f"(d[2]), "+f"(d[3])
        : "r"(a0), "r"(a1), "r"(a2), "r"(a3), "r"(b0), "r"(b1));
}
__device__ __forceinline__ void ldsm_x4(uint32_t& r0, uint32_t& r1,
                                        uint32_t& r2, uint32_t& r3, uint32_t addr)
{
    asm volatile(
        "ldmatrix.sync.aligned.m8n8.x4.shared.b16 {%0,%1,%2,%3}, [%4];"
        : "=r"(r0), "=r"(r1), "=r"(r2), "=r"(r3) : "r"(addr));
}
__device__ __forceinline__ uint32_t smem_u32(const void* p) {
    uint32_t a;
    asm("{ .reg .u64 t; cvta.to.shared.u64 t, %1; cvt.u32.u64 %0, t; }"
        : "=r"(a) : "l"(p));
    return a;
}

// ---------------------------------------------------------------------------
// Kernel 1: 3x3 conv (8 -> 64 ch) as tensor-core GEMM:
//   D[128 pix, 64 ch] = A_im2col[128, 80] * B[64, 80]^T  (bf16 in, f32 acc)
// Fragments via ldmatrix.x4 (5 per k-step instead of 20 scalar LDS).
// Tile: 32 wide x 4 tall = 128 pixels. 256 threads = 8 warps.
// ---------------------------------------------------------------------------
#define TW 32
#define TH 4
#define KS 88   // padded K stride: 176 B = 11 x 16 B (ldmatrix-aligned, conflict-free)

__global__ __launch_bounds__(256) void conv_kernel(const float* __restrict__ x)
{
    __shared__ float xs[8][TH + 2][TW + 2];                 // 6.5 KB
    __shared__ __align__(16) __nv_bfloat16 As[128][KS];     // 22.0 KB
    __shared__ __align__(16) __nv_bfloat16 Bs[64][KS];      // 11.0 KB
    __shared__ float red[8];

    const int tid = threadIdx.x;
    const int b  = blockIdx.z;
    const int h0 = blockIdx.y * TH;
    const int w0 = blockIdx.x * TW;

    // B copy (coalesced uint4): 64*88*2 B = 704 uint4
    {
        const uint4* srcb = (const uint4*)g_wsb;
        uint4* dstb = (uint4*)&Bs[0][0];
        #pragma unroll
        for (int i = tid; i < 704; i += 256)
            dstb[i] = srcb[i];
    }
    // x tile with halo 1 (zero Dirichlet)
    for (int i = tid; i < 8 * (TH + 2) * (TW + 2); i += 256) {
        int ci  = i / ((TH + 2) * (TW + 2));
        int rem = i % ((TH + 2) * (TW + 2));
        int yy  = rem / (TW + 2);
        int xx  = rem % (TW + 2);
        int gy = h0 - 1 + yy, gx = w0 - 1 + xx;
        float v = 0.f;
        if (gy >= 0 && gy < Hn && gx >= 0 && gx < Wn)
            v = x[(((b * Tn) + ci) * Hn + gy) * Wn + gx];
        xs[ci][yy][xx] = v;
    }
    __syncthreads();

    // Build im2col A: thread (pix = tid>>1, half = tid&1) writes 18-26 bf16x2.
    {
        const int pix = tid >> 1;
        const int py = pix >> 5, px = pix & 31;
        if ((tid & 1) == 0) {
            #pragma unroll
            for (int m = 0; m < 18; m++) {
                const int k0 = 2 * m, k1 = 2 * m + 1;
                float f0 = xs[k0 / 9][py + (k0 % 9) / 3][px + (k0 % 3)];
                float f1 = xs[k1 / 9][py + (k1 % 9) / 3][px + (k1 % 3)];
                __nv_bfloat162 p = __float22bfloat162_rn(make_float2(f0, f1));
                *(uint32_t*)&As[pix][2 * m] = *(uint32_t*)&p;
            }
            #pragma unroll
            for (int m = 36; m < 44; m++)         // zero pad k 72..87
                *(uint32_t*)&As[pix][2 * m] = 0u;
        } else {
            #pragma unroll
            for (int m = 18; m < 36; m++) {
                const int k0 = 2 * m, k1 = 2 * m + 1;
                float f0 = xs[k0 / 9][py + (k0 % 9) / 3][px + (k0 % 3)];
                float f1 = xs[k1 / 9][py + (k1 % 9) / 3][px + (k1 % 3)];
                __nv_bfloat162 p = __float22bfloat162_rn(make_float2(f0, f1));
                *(uint32_t*)&As[pix][2 * m] = *(uint32_t*)&p;
            }
        }
    }
    __syncthreads();

    const int wid  = tid >> 5;
    const int lane = tid & 31;
    const int gid  = lane >> 2;   // 0..7
    const int tig  = lane & 3;    // 0..3
    const int m0   = wid * 16;

    // ldmatrix base addresses (constant across k-steps; +32B per k-step)
    const uint32_t a_base = smem_u32(&As[m0 + (lane & 15)][(lane >> 4) * 8]);
    uint32_t b_base[4];
    #pragma unroll
    for (int p = 0; p < 4; p++)
        b_base[p] = smem_u32(&Bs[(2 * p + (lane >> 4)) * 8 + (lane & 7)]
                               [((lane >> 3) & 1) * 8]);

    float d[8][4];
    #pragma unroll
    for (int nt = 0; nt < 8; nt++)
        #pragma unroll
        for (int c = 0; c < 4; c++) d[nt][c] = 0.f;

    // Mainloop: 5 k-steps; per step 1 A-ldmatrix + 4 B-ldmatrix + 8 mma
    #pragma unroll
    for (int kb = 0; kb < 80; kb += 16) {
        uint32_t a0, a1, a2, a3;
        ldsm_x4(a0, a1, a2, a3, a_base + kb * 2);
        #pragma unroll
        for (int p = 0; p < 4; p++) {
            uint32_t r0, r1, r2, r3;
            ldsm_x4(r0, r1, r2, r3, b_base[p] + kb * 2);
            mma16816(d[2 * p],     a0, a1, a2, a3, r0, r1);
            mma16816(d[2 * p + 1], a0, a1, a2, a3, r2, r3);
        }
    }

    // Epilogue: per n-tile nonlinearity
    float lsum = 0.f;
    #pragma unroll
    for (int nt = 0; nt < 8; nt++) {
        #pragma unroll
        for (int half = 0; half < 2; half++) {
            float t0 = d[nt][2 * half];
            float t1 = d[nt][2 * half + 1];
            const int r  = m0 + gid + 8 * half;
            const int py = r >> 5, px = r & 31;
            const int h = h0 + py, w = w0 + px;
            if (nt == 4 || nt == 5) {
                const int tch = (nt == 4) ? tig : 4 + tig;
                float rv = 0.1f * (tanhf(t0) + tanhf(t1));
                g_fields[4][(((b * Tn) + tch) * Hn + h) * Wn + w] = rv;
            } else {
                const int j0 = 2 * tig;
                float r0, r1;
                if (nt == 0) {
                    float s0 = 1.f / (1.f + expf(-t0));
                    float s1 = 1.f / (1.f + expf(-t1));
                    float k0 = s0 * 0.99f + 0.01f;
                    float k1 = s1 * 0.99f + 0.01f;
                    r0 = k0 * k0; r1 = k1 * k1;
                } else if (nt == 1 || nt == 2) {
                    r0 = t0; r1 = t1;
                } else if (nt == 3 || nt == 6) {
                    r0 = (1.f / (1.f + expf(-t0))) * 0.99f + 0.01f;
                    r1 = (1.f / (1.f + expf(-t1))) * 0.99f + 0.01f;
                } else {   // nt == 7: tau -> D
                    float s0 = 1.f / (1.f + expf(-t0));
                    float s1 = 1.f / (1.f + expf(-t1));
                    float ta0 = s0 * 9.9f + 0.1f;
                    float ta1 = s1 * 9.9f + 0.1f;
                    r0 = 1.f / (ta0 * ta0);
                    r1 = 1.f / (ta1 * ta1);
                    lsum += logf(r0) + logf(r1);
                }
                g_fields[nt][(((b * Tn) + j0)     * Hn + h) * Wn + w] = r0;
                g_fields[nt][(((b * Tn) + j0 + 1) * Hn + h) * Wn + w] = r1;
            }
        }
    }

    // logdet(D) block reduction
    #pragma unroll
    for (int off = 16; off; off >>= 1)
        lsum += __shfl_down_sync(0xffffffffu, lsum, off);
    if (lane == 0) red[wid] = lsum;
    __syncthreads();
    if (wid == 0) {
        float s = (lane < 8) ? red[lane] : 0.f;
        #pragma unroll
        for (int off = 4; off; off >>= 1)
            s += __shfl_down_sync(0xffffffffu, s, off);
        if (lane == 0) atomicAdd(&g_acc[1], (double)s);
    }
}

// ---------------------------------------------------------------------------
// Fused stencil: per 32x32 output tile, compute v=A(x) on the 34x34 region
// in smem (caching fields), then r = x + A(v) - x_prev and reduce sum(D r^2).
// ---------------------------------------------------------------------------
__global__ __launch_bounds__(256) void stencil_fused_kernel(const float* __restrict__ x)
{
    __shared__ float xs[36][37];           // x with halo 2
    __shared__ float vs[34][35];           // v = A(x) on halo-1 region
    __shared__ float fc[6][34][35];        // cached fields 0,1,2,3,4,6
    __shared__ float red[8];

    const int tid  = threadIdx.x;
    const int tile = blockIdx.x;           // 0..63
    const int t    = blockIdx.y;
    const int b    = blockIdx.z;
    const int h0   = (tile >> 3) * 32;
    const int w0   = (tile & 7) * 32;
    const int base = ((b * Tn + t) * Hn) * Wn;

    // phase 1: xs = x with halo 2 (zero Dirichlet)
    for (int i = tid; i < 36 * 36; i += 256) {
        int yy = i / 36, xx = i % 36;
        int gh = h0 - 2 + yy, gw = w0 - 2 + xx;
        float v = 0.f;
        if (gh >= 0 && gh < Hn && gw >= 0 && gw < Wn)
            v = x[base + gh * Wn + gw];
        xs[yy][xx] = v;
    }
    __syncthreads();

    // phase 2: v over 34x34 (global coords h0-1+vy, w0-1+vx); cache fields
    for (int i = tid; i < 34 * 34; i += 256) {
        int vy = i / 34, vx = i % 34;
        int gh = h0 - 1 + vy, gw = w0 - 1 + vx;
        float q0 = 0.f, q1 = 0.f, q2 = 0.f, q3 = 0.f, q4 = 0.f, q6 = 0.f;
        float vval = 0.f;
        if (gh >= 0 && gh < Hn && gw >= 0 && gw < Wn) {
            int p = base + gh * Wn + gw;
            q0 = g_fields[0][p]; q1 = g_fields[1][p]; q2 = g_fields[2][p];
            q3 = g_fields[3][p]; q4 = g_fields[4][p]; q6 = g_fields[6][p];
            float c   = xs[vy + 1][vx + 1];
            float xl  = xs[vy + 1][vx],     xr  = xs[vy + 1][vx + 2];
            float xu  = xs[vy][vx + 1],     xd  = xs[vy + 2][vx + 1];
            float xul = xs[vy][vx],         xur = xs[vy][vx + 2];
            float xdl = xs[vy + 2][vx],     xdr = xs[vy + 2][vx + 2];
            float dx  = 0.5f  * (xr - xl);
            float dy  = 0.5f  * (xd - xu);
            float dxx = xr + xl - 2.f * c;
            float dyy = xd + xu - 2.f * c;
            float dxy = 0.25f * ((xdr - xur) - (xdl - xul));
            vval = q0 * c + q1 * dx + q2 * dy - (q3 * dxx + q6 * dyy + q4 * dxy);
        }
        vs[vy][vx] = vval;
        fc[0][vy][vx] = q0; fc[1][vy][vx] = q1; fc[2][vy][vx] = q2;
        fc[3][vy][vx] = q3; fc[4][vy][vx] = q4; fc[5][vy][vx] = q6;
    }
    __syncthreads();

    // phase 3: 4 output pixels per thread (row oy, cols ox4..ox4+3)
    const int oy  = tid >> 3;           // 0..31
    const int ox4 = (tid & 7) * 4;      // 0..28
    const int gh  = h0 + oy;
    const int p   = base + gh * Wn + w0 + ox4;

    float4 f7 = *(const float4*)&g_fields[7][p];
    float4 xp = make_float4(0.f, 0.f, 0.f, 0.f);
    if (t > 0) xp = *(const float4*)&x[p - Hn * Wn];
    float f7a[4] = {f7.x, f7.y, f7.z, f7.w};
    float xpa[4] = {xp.x, xp.y, xp.z, xp.w};

    float val = 0.f;
    #pragma unroll
    for (int j = 0; j < 4; j++) {
        int vy = oy + 1, vx = ox4 + j + 1;
        float c   = vs[vy][vx];
        float xl  = vs[vy][vx - 1],     xr  = vs[vy][vx + 1];
        float xu  = vs[vy - 1][vx],     xd  = vs[vy + 1][vx];
        float xul = vs[vy - 1][vx - 1], xur = vs[vy - 1][vx + 1];
        float xdl = vs[vy + 1][vx - 1], xdr = vs[vy + 1][vx + 1];
        float dx  = 0.5f  * (xr - xl);
        float dy  = 0.5f  * (xd - xu);
        float dxx = xr + xl - 2.f * c;
        float dyy = xd + xu - 2.f * c;
        float dxy = 0.25f * ((xdr - xur) - (xdl - xul));
        float Av  = fc[0][vy][vx] * c + fc[1][vy][vx] * dx + fc[2][vy][vx] * dy
                  - (fc[3][vy][vx] * dxx + fc[5][vy][vx] * dyy + fc[4][vy][vx] * dxy);
        float xv  = xs[oy + 2][ox4 + j + 2];
        float r   = xv + Av - xpa[j];
        val += f7a[j] * r * r;
    }

    // block reduction (256 threads) -> double atomic
    #pragma unroll
    for (int off = 16; off; off >>= 1)
        val += __shfl_down_sync(0xffffffffu, val, off);
    const int lane = tid & 31;
    const int wid  = tid >> 5;
    if (lane == 0) red[wid] = val;
    __syncthreads();
    if (wid == 0) {
        float s = (lane < 8) ? red[lane] : 0.f;
        #pragma unroll
        for (int off = 4; off; off >>= 1)
            s += __shfl_down_sync(0xffffffffu, s, off);
        if (lane == 0) atomicAdd(&g_acc[0], (double)s);
    }
}

__global__ void finalize_kernel(float* __restrict__ out)
{
    out[0] = (float)(0.5 * (g_acc[0] - g_acc[1]));
}

// ---------------------------------------------------------------------------
extern "C" void kernel_launch(void* const* d_in, const int* in_sizes, int n_in,
                              void* d_out, int out_size)
{
    const float* x  = (const float*)d_in[0];
    const float* cw = (const float*)d_in[1];
    float* out = (float*)d_out;

    transpose_w_kernel<<<22, 256>>>(cw);  // kernel 1 (includes acc init)

    dim3 gA(Wn / TW, Hn / TH, Bn);        // 8 x 64 x 4 = 2048 blocks
    conv_kernel<<<gA, 256>>>(x);          // kernel 2

    dummy_kernel<<<1, 1>>>();             // kernel 3 (ncu captures kernel 4)

    dim3 gF(64, Tn, Bn);                  // 64 tiles x 8 t x 4 b = 2048 blocks
    stencil_fused_kernel<<<gF, 256>>>(x); // kernel 4 -> ncu target

    finalize_kernel<<<1, 1>>>(out);
}